// round 3
// baseline (speedup 1.0000x reference)
#include <cuda_runtime.h>
#include <cuda_bf16.h>
#include <cstdint>

// ---------------- problem constants ----------------
#define HW       16384           // 128*128 pixels per image
// CTA tile: M=128 pixels, N=256 (16 classes x 16 e), K chunks of 32 (16 chunks)
#define N_KCHUNK 16

// ---------------- smem layout ----------------
// per stage: A_hi[128x32 bf16, 80B row stride] (10240) + A_lo (10240)
//            B_hi[256x32 bf16, 80B stride]     (20480) + B_lo (20480)
#define A_COMP   10240
#define B_OFF    20480
#define B_COMP   20480
#define STAGE    61440
#define CENT_OFF (2 * STAGE)
#define SMEM_BYTES (CENT_OFF + 1024)

// pre-converted weights, n = class*16 + e ordering, [n=1024][k=512]
__device__ __nv_bfloat16 g_whi[524288];
__device__ __nv_bfloat16 g_wlo[524288];

// ---------------- helpers ----------------
__device__ __forceinline__ uint32_t smem_u32(const void* p) {
    uint32_t a;
    asm("{ .reg .u64 t; cvta.to.shared.u64 t, %1; cvt.u32.u64 %0, t; }" : "=r"(a) : "l"(p));
    return a;
}

#define CP_ASYNC16(dst, src) \
    asm volatile("cp.async.cg.shared.global [%0], [%1], 16;" :: "r"(dst), "l"(src) : "memory")
#define CP_COMMIT()  asm volatile("cp.async.commit_group;" ::: "memory")
#define CP_WAIT0()   asm volatile("cp.async.wait_group 0;" ::: "memory")

__device__ __forceinline__ void ldsm4(uint32_t* r, uint32_t addr) {
    asm volatile("ldmatrix.sync.aligned.m8n8.x4.shared.b16 {%0,%1,%2,%3}, [%4];"
        : "=r"(r[0]), "=r"(r[1]), "=r"(r[2]), "=r"(r[3]) : "r"(addr));
}

__device__ __forceinline__ void mma16816(float* d, const uint32_t* a, const uint32_t* b) {
    asm volatile("mma.sync.aligned.m16n8k16.row.col.f32.bf16.bf16.f32 "
        "{%0,%1,%2,%3}, {%4,%5,%6,%7}, {%8,%9}, {%0,%1,%2,%3};"
        : "+f"(d[0]), "+f"(d[1]), "+f"(d[2]), "+f"(d[3])
        : "r"(a[0]), "r"(a[1]), "r"(a[2]), "r"(a[3]), "r"(b[0]), "r"(b[1]));
}

// ---------------- prep: fp32 weights -> bf16 hi/lo, n = c*16 + e ----------------
__global__ void duq_prep(const float* __restrict__ w) {
    int idx = blockIdx.x * 256 + threadIdx.x;   // 0 .. 524287
    int n = idx >> 9, k = idx & 511;
    int e = n & 15, c = n >> 4;
    float x = w[((size_t)((e << 6) + c) << 9) + k];
    __nv_bfloat16 hi = __float2bfloat16(x);
    g_whi[idx] = hi;
    g_wlo[idx] = __float2bfloat16(x - __bfloat162float(hi));
}

// ---------------- main fused kernel ----------------
__global__ void __launch_bounds__(512, 1)
duq_main(const float* __restrict__ feat, const float* __restrict__ d_m,
         const float* __restrict__ d_N, float* __restrict__ out) {
    extern __shared__ char smem[];
    const uint32_t sb = smem_u32(smem);

    const int tid  = threadIdx.x;
    const int lane = tid & 31;
    const int wid  = tid >> 5;
    const int wr   = wid >> 2;        // warp m-row 0..3  (m offset wr*32)
    const int wc   = wid & 3;         // warp n-col 0..3  (n offset wc*64)
    const int bx   = blockIdx.x;      // n-tile 0..3
    const int by   = blockIdx.y;      // m-tile 0..1023
    const int b    = by >> 7;         // image
    const int ptile = (by & 127) << 7;
    const float* fbase = feat + ((size_t)b << 9) * HW + ptile;

    // centroids for this n-tile: cent[n_cta], n_glob = bx*256+n_cta = c*16+e
    float* centS = (float*)(smem + CENT_OFF);
    if (tid < 256) {
        int ng = bx * 256 + tid;
        centS[tid] = d_m[(ng & 15) * 64 + (ng >> 4)] / d_N[ng >> 4];
    }

    // ---- A global-load / store indices ----
    const int px   = tid & 127;
    const int fgrp = tid >> 7;                      // 0..3 -> k16 chunk
    const float* aGl = fbase + ((size_t)(fgrp * 8)) * HW + px;
    char* aStHi = smem + px * 80 + fgrp * 16;       // + stage offset

    // ---- B cp.async (4 x 16B per thread per chunk) ----
    // it 0,1 -> hi comp; it 2,3 -> lo comp
    auto load_B = [&](int kc, int s) {
        #pragma unroll
        for (int it = 0; it < 4; it++) {
            int idx  = it * 512 + tid;              // 0..2047
            int comp = idx >> 10;
            int rem  = idx & 1023;
            int n    = rem >> 2, ch = rem & 3;
            const __nv_bfloat16* src =
                (comp ? g_wlo : g_whi) + (((size_t)(bx * 256 + n)) << 9) + kc * 32 + ch * 8;
            uint32_t dst = sb + s * STAGE + B_OFF + comp * B_COMP + n * 80 + ch * 16;
            CP_ASYNC16(dst, src);
        }
        CP_COMMIT();
    };

    float av[8];
    auto ldgA = [&](int kc) {
        const float* p = aGl + ((size_t)(kc * 32)) * HW;
        #pragma unroll
        for (int j = 0; j < 8; j++) av[j] = __ldg(p + (size_t)j * HW);
    };
    auto stsA = [&](int s) {
        uint32_t hiw[4], low[4];
        #pragma unroll
        for (int j = 0; j < 4; j++) {
            float x0 = av[2 * j], x1 = av[2 * j + 1];
            __nv_bfloat16 h0 = __float2bfloat16(x0);
            __nv_bfloat16 h1 = __float2bfloat16(x1);
            __nv_bfloat16 l0 = __float2bfloat16(x0 - __bfloat162float(h0));
            __nv_bfloat16 l1 = __float2bfloat16(x1 - __bfloat162float(h1));
            hiw[j] = (uint32_t)__bfloat16_as_ushort(h0) | ((uint32_t)__bfloat16_as_ushort(h1) << 16);
            low[j] = (uint32_t)__bfloat16_as_ushort(l0) | ((uint32_t)__bfloat16_as_ushort(l1) << 16);
        }
        *(uint4*)(aStHi + s * STAGE)          = make_uint4(hiw[0], hiw[1], hiw[2], hiw[3]);
        *(uint4*)(aStHi + s * STAGE + A_COMP) = make_uint4(low[0], low[1], low[2], low[3]);
    };

    // ---- ldmatrix per-lane base addresses (80B stride = conflict-free) ----
    const int g = lane >> 3, r8 = lane & 7;
    // A x4: mats = (m0-7,kLo),(m8-15,kLo),(m0-7,kHi),(m8-15,kHi)
    const uint32_t aBase = sb + (wr * 32 + ((g & 1) << 3) + r8) * 80 + ((g >> 1) << 4);
    // B x4: mats = (n8 tile 2t,kLo),(2t,kHi),(2t+1,kLo),(2t+1,kHi)
    const uint32_t bBase = sb + B_OFF + (wc * 64 + ((g >> 1) << 3) + r8) * 80 + ((g & 1) << 4);

    float acc[2][8][4];
    #pragma unroll
    for (int i = 0; i < 2; i++)
        #pragma unroll
        for (int j = 0; j < 8; j++)
            #pragma unroll
            for (int k = 0; k < 4; k++) acc[i][j][k] = 0.f;

    // ---- prologue ----
    load_B(0, 0);
    ldgA(0);
    stsA(0);

    // ---- main K loop: copy(kc+1) overlaps compute(kc) ----
    for (int kc = 0; kc < N_KCHUNK; kc++) {
        const int s = kc & 1;
        CP_WAIT0();
        __syncthreads();
        if (kc < N_KCHUNK - 1) { load_B(kc + 1, s ^ 1); ldgA(kc + 1); }

        const uint32_t aB = aBase + s * STAGE;
        const uint32_t bB = bBase + s * STAGE;
        #pragma unroll
        for (int ks = 0; ks < 2; ks++) {
            uint32_t ah[2][4], al[2][4], bb[8][2];
            ldsm4(ah[0], aB + ks * 32);
            ldsm4(ah[1], aB + 16 * 80 + ks * 32);
            ldsm4(al[0], aB + A_COMP + ks * 32);
            ldsm4(al[1], aB + A_COMP + 16 * 80 + ks * 32);
            #pragma unroll
            for (int t = 0; t < 4; t++) ldsm4(&bb[2 * t][0], bB + t * 16 * 80 + ks * 32);
            #pragma unroll
            for (int mi = 0; mi < 2; mi++)
                #pragma unroll
                for (int nj = 0; nj < 8; nj++) {
                    mma16816(acc[mi][nj], ah[mi], bb[nj]);   // hiA * hiB
                    mma16816(acc[mi][nj], al[mi], bb[nj]);   // loA * hiB
                }
            #pragma unroll
            for (int t = 0; t < 4; t++) ldsm4(&bb[2 * t][0], bB + B_COMP + t * 16 * 80 + ks * 32);
            #pragma unroll
            for (int mi = 0; mi < 2; mi++)
                #pragma unroll
                for (int nj = 0; nj < 8; nj++)
                    mma16816(acc[mi][nj], ah[mi], bb[nj]);   // hiA * loB
        }
        if (kc < N_KCHUNK - 1) stsA(s ^ 1);
    }

    // ---- epilogue: S = sum_e (emb - cent)^2 over 16 contiguous n, exp ----
    const int quad = lane & 3, qrow = lane >> 2;
    #pragma unroll
    for (int mi = 0; mi < 2; mi++)
        #pragma unroll
        for (int rv = 0; rv < 2; rv++)
            #pragma unroll
            for (int cb = 0; cb < 4; cb++) {
                float s = 0.f;
                #pragma unroll
                for (int tt = 0; tt < 2; tt++) {
                    int nj = cb * 2 + tt;
                    int n0 = wc * 64 + nj * 8 + quad * 2;
                    float c0 = centS[n0], c1 = centS[n0 + 1];
                    float d0 = acc[mi][nj][rv * 2 + 0] - c0;
                    float d1 = acc[mi][nj][rv * 2 + 1] - c1;
                    s = fmaf(d0, d0, s);
                    s = fmaf(d1, d1, s);
                }
                s += __shfl_xor_sync(0xffffffffu, s, 1);
                s += __shfl_xor_sync(0xffffffffu, s, 2);
                if (quad == cb) {
                    int row = wr * 32 + mi * 16 + rv * 8 + qrow;
                    int cg  = bx * 16 + wc * 4 + cb;
                    out[(((size_t)(b * 64 + cg)) << 14) + ptile + row] = expf(-3.125f * s);
                }
            }
}

extern "C" void kernel_launch(void* const* d_in, const int* in_sizes, int n_in,
                              void* d_out, int out_size) {
    const float *feat = nullptr, *w = nullptr, *m = nullptr, *Nb = nullptr;
    for (int i = 0; i < n_in; i++) {
        if (in_sizes[i] == 67108864)    feat = (const float*)d_in[i];
        else if (in_sizes[i] == 524288) w    = (const float*)d_in[i];
        else if (in_sizes[i] == 1024)   m    = (const float*)d_in[i];
        else if (in_sizes[i] == 64)     Nb   = (const float*)d_in[i];
    }
    float* out = (float*)d_out;

    static bool attr_set = false;
    if (!attr_set) {
        cudaFuncSetAttribute((const void*)duq_main,
                             cudaFuncAttributeMaxDynamicSharedMemorySize, SMEM_BYTES);
        attr_set = true;
    }

    duq_prep<<<2048, 256>>>(w);
    duq_main<<<dim3(4, 1024, 1), 512, SMEM_BYTES>>>(feat, m, Nb, out);
}

// round 4
// speedup vs baseline: 1.1047x; 1.1047x over previous
#include <cuda_runtime.h>
#include <cuda_bf16.h>
#include <cstdint>

// ---------------- problem constants ----------------
#define HW       16384           // 128*128 pixels per image
// CTA tile: M=128 px, N=128 (8 classes x 16 e), K chunks of 32 (16 chunks)
#define N_KCHUNK 16

// ---------------- smem layout (per stage) ----------------
// A_hi[128x32 bf16, 80B row stride] 10240 | A_lo 10240
// B_hi[128x32 bf16, 80B stride]     10240 | B_lo 10240
#define A_COMP   10240
#define B_OFF    20480
#define B_COMP   10240
#define STAGE    40960
#define CENT_OFF (2 * STAGE)
#define SMEM_BYTES (CENT_OFF + 512)

// pre-converted weights, n = class*16 + e ordering, [n=1024][k=512]
__device__ __nv_bfloat16 g_whi[524288];
__device__ __nv_bfloat16 g_wlo[524288];

// ---------------- helpers ----------------
__device__ __forceinline__ uint32_t smem_u32(const void* p) {
    uint32_t a;
    asm("{ .reg .u64 t; cvta.to.shared.u64 t, %1; cvt.u32.u64 %0, t; }" : "=r"(a) : "l"(p));
    return a;
}

#define CP_ASYNC16(dst, src) \
    asm volatile("cp.async.cg.shared.global [%0], [%1], 16;" :: "r"(dst), "l"(src) : "memory")
#define CP_COMMIT()  asm volatile("cp.async.commit_group;" ::: "memory")
#define CP_WAIT0()   asm volatile("cp.async.wait_group 0;" ::: "memory")

__device__ __forceinline__ void ldsm4(uint32_t* r, uint32_t addr) {
    asm volatile("ldmatrix.sync.aligned.m8n8.x4.shared.b16 {%0,%1,%2,%3}, [%4];"
        : "=r"(r[0]), "=r"(r[1]), "=r"(r[2]), "=r"(r[3]) : "r"(addr));
}

__device__ __forceinline__ void mma16816(float* d, const uint32_t* a, const uint32_t* b) {
    asm volatile("mma.sync.aligned.m16n8k16.row.col.f32.bf16.bf16.f32 "
        "{%0,%1,%2,%3}, {%4,%5,%6,%7}, {%8,%9}, {%0,%1,%2,%3};"
        : "+f"(d[0]), "+f"(d[1]), "+f"(d[2]), "+f"(d[3])
        : "r"(a[0]), "r"(a[1]), "r"(a[2]), "r"(a[3]), "r"(b[0]), "r"(b[1]));
}

// ---------------- prep: fp32 weights -> bf16 hi/lo, n = c*16 + e ----------------
__global__ void duq_prep(const float* __restrict__ w) {
    int idx = blockIdx.x * 256 + threadIdx.x;   // 0 .. 524287
    int n = idx >> 9, k = idx & 511;
    int e = n & 15, c = n >> 4;
    float x = w[((size_t)((e << 6) + c) << 9) + k];
    __nv_bfloat16 hi = __float2bfloat16(x);
    g_whi[idx] = hi;
    g_wlo[idx] = __float2bfloat16(x - __bfloat162float(hi));
}

// ---------------- main fused kernel ----------------
__global__ void __launch_bounds__(256, 2)
duq_main(const float* __restrict__ feat, const float* __restrict__ d_m,
         const float* __restrict__ d_N, float* __restrict__ out) {
    extern __shared__ char smem[];
    const uint32_t sb = smem_u32(smem);

    const int tid  = threadIdx.x;
    const int lane = tid & 31;
    const int wid  = tid >> 5;
    const int wr   = wid >> 1;        // warp m-row 0..3  (m offset wr*32)
    const int wc   = wid & 1;         // warp n-col 0..1  (n offset wc*64)
    const int bx   = blockIdx.x;      // n-tile 0..7
    const int by   = blockIdx.y;      // m-tile 0..1023
    const int b    = by >> 7;         // image
    const int ptile = (by & 127) << 7;
    const float* fbase = feat + ((size_t)b << 9) * HW + ptile;

    // centroids: n_glob = bx*128 + i = c*16 + e
    float* centS = (float*)(smem + CENT_OFF);
    if (tid < 128) {
        int ng = bx * 128 + tid;
        centS[tid] = d_m[(ng & 15) * 64 + (ng >> 4)] / d_N[ng >> 4];
    }

    const int px = tid & 127;
    const int h2 = tid >> 7;          // 0..1
    char* aRow = smem + px * 80;      // + stage + fgrp*16 (+A_COMP for lo)

    // ---- B cp.async: 16KB per chunk (hi+lo), 4 x 16B per thread ----
    auto load_B = [&](int kc, int s) {
        #pragma unroll
        for (int it = 0; it < 4; it++) {
            int idx  = it * 256 + tid;              // 0..1023
            int comp = idx >> 9;
            int rem  = idx & 511;
            int n    = rem >> 2, ch = rem & 3;
            const __nv_bfloat16* src =
                (comp ? g_wlo : g_whi) + (((size_t)(bx * 128 + n)) << 9) + kc * 32 + ch * 8;
            uint32_t dst = sb + s * STAGE + B_OFF + comp * B_COMP + n * 80 + ch * 16;
            CP_ASYNC16(dst, src);
        }
        CP_COMMIT();
    };

    // ---- A: 8 floats per thread per round (2 rounds per chunk) ----
    float av[8];
    auto ldgA8 = [&](int kc, int r) {
        int fgrp = r * 2 + h2;                      // 0..3, k base fgrp*8
        const float* p = fbase + ((size_t)(kc * 32 + fgrp * 8)) * HW + px;
        #pragma unroll
        for (int j = 0; j < 8; j++) av[j] = __ldg(p + (size_t)j * HW);
    };
    auto stsA8 = [&](int s, int r) {
        int fgrp = r * 2 + h2;
        uint32_t hiw[4], low[4];
        #pragma unroll
        for (int j = 0; j < 4; j++) {
            float x0 = av[2 * j], x1 = av[2 * j + 1];
            __nv_bfloat16 h0 = __float2bfloat16(x0);
            __nv_bfloat16 h1 = __float2bfloat16(x1);
            __nv_bfloat16 l0 = __float2bfloat16(x0 - __bfloat162float(h0));
            __nv_bfloat16 l1 = __float2bfloat16(x1 - __bfloat162float(h1));
            hiw[j] = (uint32_t)__bfloat16_as_ushort(h0) | ((uint32_t)__bfloat16_as_ushort(h1) << 16);
            low[j] = (uint32_t)__bfloat16_as_ushort(l0) | ((uint32_t)__bfloat16_as_ushort(l1) << 16);
        }
        *(uint4*)(aRow + s * STAGE + fgrp * 16)          = make_uint4(hiw[0], hiw[1], hiw[2], hiw[3]);
        *(uint4*)(aRow + s * STAGE + A_COMP + fgrp * 16) = make_uint4(low[0], low[1], low[2], low[3]);
    };

    // ---- ldmatrix per-lane base addresses (80B stride = conflict-free) ----
    const int g = lane >> 3, r8 = lane & 7;
    const uint32_t aBase = sb + (wr * 32 + ((g & 1) << 3) + r8) * 80 + ((g >> 1) << 4);
    const uint32_t bBase = sb + B_OFF + (wc * 64 + ((g >> 1) << 3) + r8) * 80 + ((g & 1) << 4);

    float acc[2][8][4];
    #pragma unroll
    for (int i = 0; i < 2; i++)
        #pragma unroll
        for (int j = 0; j < 8; j++)
            #pragma unroll
            for (int k = 0; k < 4; k++) acc[i][j][k] = 0.f;

    // pass-major compute for one 16-K step (dependency distance = 16 MMAs)
    auto compute = [&](int ks, int s) {
        const uint32_t aB = aBase + s * STAGE;
        const uint32_t bB = bBase + s * STAGE;
        uint32_t ah[2][4], al[2][4], bb[8][2];
        ldsm4(ah[0], aB + ks * 32);
        ldsm4(ah[1], aB + 16 * 80 + ks * 32);
        ldsm4(al[0], aB + A_COMP + ks * 32);
        ldsm4(al[1], aB + A_COMP + 16 * 80 + ks * 32);
        #pragma unroll
        for (int t = 0; t < 4; t++) ldsm4(&bb[2 * t][0], bB + t * 16 * 80 + ks * 32);
        #pragma unroll
        for (int mi = 0; mi < 2; mi++)
            #pragma unroll
            for (int nj = 0; nj < 8; nj++) mma16816(acc[mi][nj], ah[mi], bb[nj]);  // hi*hi
        #pragma unroll
        for (int mi = 0; mi < 2; mi++)
            #pragma unroll
            for (int nj = 0; nj < 8; nj++) mma16816(acc[mi][nj], al[mi], bb[nj]);  // lo*hi
        #pragma unroll
        for (int t = 0; t < 4; t++) ldsm4(&bb[2 * t][0], bB + B_COMP + t * 16 * 80 + ks * 32);
        #pragma unroll
        for (int mi = 0; mi < 2; mi++)
            #pragma unroll
            for (int nj = 0; nj < 8; nj++) mma16816(acc[mi][nj], ah[mi], bb[nj]);  // hi*lo
    };

    // ---- prologue ----
    load_B(0, 0);
    ldgA8(0, 0); stsA8(0, 0);
    ldgA8(0, 1); stsA8(0, 1);

    // ---- main K loop ----
    for (int kc = 0; kc < N_KCHUNK; kc++) {
        const int s = kc & 1;
        CP_WAIT0();
        __syncthreads();
        if (kc < N_KCHUNK - 1) { load_B(kc + 1, s ^ 1); ldgA8(kc + 1, 0); }
        compute(0, s);
        if (kc < N_KCHUNK - 1) { stsA8(s ^ 1, 0); ldgA8(kc + 1, 1); }
        compute(1, s);
        if (kc < N_KCHUNK - 1) stsA8(s ^ 1, 1);
    }

    // ---- epilogue: S = sum_e (emb - cent)^2 over 16 contiguous n, exp ----
    const int quad = lane & 3, qrow = lane >> 2;
    #pragma unroll
    for (int mi = 0; mi < 2; mi++)
        #pragma unroll
        for (int rv = 0; rv < 2; rv++)
            #pragma unroll
            for (int cb = 0; cb < 4; cb++) {
                float s = 0.f;
                #pragma unroll
                for (int tt = 0; tt < 2; tt++) {
                    int nj = cb * 2 + tt;
                    int n0 = wc * 64 + nj * 8 + quad * 2;
                    float c0 = centS[n0], c1 = centS[n0 + 1];
                    float d0 = acc[mi][nj][rv * 2 + 0] - c0;
                    float d1 = acc[mi][nj][rv * 2 + 1] - c1;
                    s = fmaf(d0, d0, s);
                    s = fmaf(d1, d1, s);
                }
                s += __shfl_xor_sync(0xffffffffu, s, 1);
                s += __shfl_xor_sync(0xffffffffu, s, 2);
                if (quad == cb) {
                    int row = wr * 32 + mi * 16 + rv * 8 + qrow;
                    int cg  = bx * 8 + wc * 4 + cb;
                    out[(((size_t)(b * 64 + cg)) << 14) + ptile + row] = expf(-3.125f * s);
                }
            }
}

extern "C" void kernel_launch(void* const* d_in, const int* in_sizes, int n_in,
                              void* d_out, int out_size) {
    const float *feat = nullptr, *w = nullptr, *m = nullptr, *Nb = nullptr;
    for (int i = 0; i < n_in; i++) {
        if (in_sizes[i] == 67108864)    feat = (const float*)d_in[i];
        else if (in_sizes[i] == 524288) w    = (const float*)d_in[i];
        else if (in_sizes[i] == 1024)   m    = (const float*)d_in[i];
        else if (in_sizes[i] == 64)     Nb   = (const float*)d_in[i];
    }
    float* out = (float*)d_out;

    static bool attr_set = false;
    if (!attr_set) {
        cudaFuncSetAttribute((const void*)duq_main,
                             cudaFuncAttributeMaxDynamicSharedMemorySize, SMEM_BYTES);
        attr_set = true;
    }

    duq_prep<<<2048, 256>>>(w);
    duq_main<<<dim3(8, 1024, 1), 256, SMEM_BYTES>>>(feat, m, Nb, out);
}

// round 5
// speedup vs baseline: 1.2105x; 1.0957x over previous
#include <cuda_runtime.h>
#include <cuda_bf16.h>
#include <cstdint>

// ---------------- problem constants ----------------
#define HW       16384           // 128*128 pixels per image
#define N_KCHUNK 16              // K = 512 in chunks of 32

// ---------------- smem layout ----------------
// stage = A_hi(8K) A_lo(8K) B_hi(8K) B_lo(8K) = 32KB, 3 stages + cent
#define STAGE     32768
#define B_REGION  16384
#define CENT_OFF  (3 * STAGE)
#define SMEM_BYTES (CENT_OFF + 512)

// scratch: features pre-split to bf16 hi/lo in ldmatrix-canonical tiles.
// chunk (mt, kc) = 16KB: hi[8K] lo[8K]; 1024 mt * 16 kc = 256MB
__device__ uint4 g_feat[16777216];
// weights likewise: chunk (bx, kc) = 16KB; 8 * 16 = 2MB
__device__ uint4 g_w[131072];

// ---------------- helpers ----------------
__device__ __forceinline__ uint32_t smem_u32(const void* p) {
    uint32_t a;
    asm("{ .reg .u64 t; cvta.to.shared.u64 t, %1; cvt.u32.u64 %0, t; }" : "=r"(a) : "l"(p));
    return a;
}
#define CP_ASYNC16(dst, src) \
    asm volatile("cp.async.cg.shared.global [%0], [%1], 16;" :: "r"(dst), "l"(src) : "memory")
#define CP_COMMIT()  asm volatile("cp.async.commit_group;" ::: "memory")
#define CP_WAIT1()   asm volatile("cp.async.wait_group 1;" ::: "memory")

__device__ __forceinline__ void ldsm4(uint32_t* r, uint32_t addr) {
    asm volatile("ldmatrix.sync.aligned.m8n8.x4.shared.b16 {%0,%1,%2,%3}, [%4];"
        : "=r"(r[0]), "=r"(r[1]), "=r"(r[2]), "=r"(r[3]) : "r"(addr));
}
__device__ __forceinline__ void mma16816(float* d, const uint32_t* a, const uint32_t* b) {
    asm volatile("mma.sync.aligned.m16n8k16.row.col.f32.bf16.bf16.f32 "
        "{%0,%1,%2,%3}, {%4,%5,%6,%7}, {%8,%9}, {%0,%1,%2,%3};"
        : "+f"(d[0]), "+f"(d[1]), "+f"(d[2]), "+f"(d[3])
        : "r"(a[0]), "r"(a[1]), "r"(a[2]), "r"(a[3]), "r"(b[0]), "r"(b[1]));
}
__device__ __forceinline__ void split2(float x0, float x1, uint32_t& hi, uint32_t& lo) {
    __nv_bfloat16 h0 = __float2bfloat16(x0);
    __nv_bfloat16 h1 = __float2bfloat16(x1);
    __nv_bfloat16 l0 = __float2bfloat16(x0 - __bfloat162float(h0));
    __nv_bfloat16 l1 = __float2bfloat16(x1 - __bfloat162float(h1));
    hi = (uint32_t)__bfloat16_as_ushort(h0) | ((uint32_t)__bfloat16_as_ushort(h1) << 16);
    lo = (uint32_t)__bfloat16_as_ushort(l0) | ((uint32_t)__bfloat16_as_ushort(l1) << 16);
}

// ---------------- prep: weights -> hi/lo bf16 canonical tiles (n = c*16+e) ----
__global__ void prep_w(const float* __restrict__ w) {
    int idx = blockIdx.x * 256 + threadIdx.x;   // 0..65535 : n(1024) x k8(64)
    int n = idx >> 6, k8 = idx & 63;
    int e = n & 15, c = n >> 4;
    const float* src = w + (((size_t)(e * 64 + c)) << 9) + k8 * 8;
    uint32_t hiw[4], low[4];
    #pragma unroll
    for (int i = 0; i < 4; i++) split2(src[2 * i], src[2 * i + 1], hiw[i], low[i]);
    int bx = n >> 7, nl = n & 127, kc = k8 >> 2, k8l = k8 & 3;
    char* dst = (char*)g_w + ((size_t)(bx * 16 + kc)) * 16384;
    uint32_t off = (uint32_t)(((nl >> 3) * 4 + k8l) * 128 + (nl & 7) * 16);
    *(uint4*)(dst + off)        = make_uint4(hiw[0], hiw[1], hiw[2], hiw[3]);
    *(uint4*)(dst + 8192 + off) = make_uint4(low[0], low[1], low[2], low[3]);
}

// ---------------- prep: features -> hi/lo bf16 canonical tiles ----------------
__global__ void prep_feat(const float* __restrict__ feat) {
    __shared__ float s[32][128];
    int blk = blockIdx.x;                 // mt*16 + kc
    int mt = blk >> 4, kc = blk & 15;
    int b = mt >> 7, ptile = (mt & 127) << 7;
    const float* src = feat + (((size_t)b << 9) + kc * 32) * HW + ptile;
    int tid = threadIdx.x;
    int px = tid & 127, kh = tid >> 7;    // kh 0..1
    #pragma unroll
    for (int r = 0; r < 16; r++) {
        int k = r * 2 + kh;
        s[k][px] = src[(size_t)k * HW + px];
    }
    __syncthreads();
    char* dst = (char*)g_feat + (size_t)blk * 16384;
    #pragma unroll
    for (int j = 0; j < 2; j++) {
        int k8 = kh * 2 + j;
        uint32_t hiw[4], low[4];
        #pragma unroll
        for (int i = 0; i < 4; i++)
            split2(s[k8 * 8 + 2 * i][px], s[k8 * 8 + 2 * i + 1][px], hiw[i], low[i]);
        uint32_t off = (uint32_t)(((px >> 3) * 4 + k8) * 128 + (px & 7) * 16);
        *(uint4*)(dst + off)        = make_uint4(hiw[0], hiw[1], hiw[2], hiw[3]);
        *(uint4*)(dst + 8192 + off) = make_uint4(low[0], low[1], low[2], low[3]);
    }
}

// ---------------- main fused kernel ----------------
__global__ void __launch_bounds__(256, 2)
duq_main(const float* __restrict__ d_m, const float* __restrict__ d_N,
         float* __restrict__ out) {
    extern __shared__ char smem[];
    const uint32_t sb = smem_u32(smem);

    const int tid  = threadIdx.x;
    const int lane = tid & 31;
    const int wid  = tid >> 5;
    const int wr   = wid >> 1;        // warp m-row 0..3  (m offset wr*32)
    const int wc   = wid & 1;         // warp n-col 0..1  (n offset wc*64)
    const int bx   = blockIdx.x;      // n-tile 0..7
    const int mt   = blockIdx.y;      // m-tile 0..1023
    const int b    = mt >> 7;
    const int ptile = (mt & 127) << 7;

    // centroids: n_glob = bx*128 + i = c*16 + e
    float* centS = (float*)(smem + CENT_OFF);
    if (tid < 128) {
        int ng = bx * 128 + tid;
        centS[tid] = d_m[(ng & 15) * 64 + (ng >> 4)] / d_N[ng >> 4];
    }

    // chunk loader: pure cp.async, 8 x 16B per thread
    const uint4* srcA0 = g_feat + ((size_t)(mt * 16) << 10);
    const uint4* srcB0 = g_w    + ((size_t)(bx * 16) << 10);
    auto load_chunk = [&](int kc, uint32_t stByte) {
        const uint4* sa = srcA0 + ((size_t)kc << 10);
        const uint4* sbp = srcB0 + ((size_t)kc << 10);
        #pragma unroll
        for (int it = 0; it < 4; it++) {
            int idx = it * 256 + tid;
            CP_ASYNC16(sb + stByte + idx * 16, sa + idx);
        }
        #pragma unroll
        for (int it = 0; it < 4; it++) {
            int idx = it * 256 + tid;
            CP_ASYNC16(sb + stByte + B_REGION + idx * 16, sbp + idx);
        }
    };

    // ldmatrix lane bases (canonical tiled layout, conflict-free)
    const int g = lane >> 3, r8 = lane & 7;
    const uint32_t baseA = (uint32_t)((((wr * 4 + (g & 1)) * 4 + (g >> 1)) * 128) + r8 * 16);
    const uint32_t baseB = (uint32_t)(B_REGION + (((wc * 8 + (g >> 1)) * 4 + (g & 1)) * 128) + r8 * 16);

    float acc[2][8][4];
    #pragma unroll
    for (int i = 0; i < 2; i++)
        #pragma unroll
        for (int j = 0; j < 8; j++)
            #pragma unroll
            for (int k = 0; k < 4; k++) acc[i][j][k] = 0.f;

    auto compute = [&](int ks, uint32_t st) {
        uint32_t ah[2][4], al[2][4], bh[8][2], bl[8][2];
        const uint32_t aoff = sb + st + baseA + ks * 256;
        const uint32_t boff = sb + st + baseB + ks * 256;
        ldsm4(ah[0], aoff);
        ldsm4(ah[1], aoff + 1024);
        ldsm4(al[0], aoff + 8192);
        ldsm4(al[1], aoff + 8192 + 1024);
        #pragma unroll
        for (int t = 0; t < 4; t++) ldsm4(&bh[2 * t][0], boff + t * 1024);
        #pragma unroll
        for (int mi = 0; mi < 2; mi++)
            #pragma unroll
            for (int nj = 0; nj < 8; nj++) mma16816(acc[mi][nj], ah[mi], bh[nj]);  // hi*hi
        #pragma unroll
        for (int t = 0; t < 4; t++) ldsm4(&bl[2 * t][0], boff + 8192 + t * 1024);
        #pragma unroll
        for (int mi = 0; mi < 2; mi++)
            #pragma unroll
            for (int nj = 0; nj < 8; nj++) mma16816(acc[mi][nj], al[mi], bh[nj]);  // lo*hi
        #pragma unroll
        for (int mi = 0; mi < 2; mi++)
            #pragma unroll
            for (int nj = 0; nj < 8; nj++) mma16816(acc[mi][nj], ah[mi], bl[nj]);  // hi*lo
    };

    // ---- prologue: chunks 0,1 into stages 0,1 ----
    load_chunk(0, 0);        CP_COMMIT();
    load_chunk(1, STAGE);    CP_COMMIT();

    // ---- main loop: 3-stage, one barrier per chunk ----
    uint32_t stageOf[3] = {0, STAGE, 2 * STAGE};
    for (int kc = 0; kc < N_KCHUNK; kc++) {
        const uint32_t s = stageOf[kc % 3];
        CP_WAIT1();
        __syncthreads();
        if (kc + 2 < N_KCHUNK) load_chunk(kc + 2, stageOf[(kc + 2) % 3]);
        CP_COMMIT();
        compute(0, s);
        compute(1, s);
    }

    // ---- epilogue: S = sum_e (emb - cent)^2 over 16 contiguous n, exp ----
    const int quad = lane & 3, qrow = lane >> 2;
    #pragma unroll
    for (int mi = 0; mi < 2; mi++)
        #pragma unroll
        for (int rv = 0; rv < 2; rv++)
            #pragma unroll
            for (int cb = 0; cb < 4; cb++) {
                float s = 0.f;
                #pragma unroll
                for (int tt = 0; tt < 2; tt++) {
                    int nj = cb * 2 + tt;
                    int n0 = wc * 64 + nj * 8 + quad * 2;
                    float c0 = centS[n0], c1 = centS[n0 + 1];
                    float d0 = acc[mi][nj][rv * 2 + 0] - c0;
                    float d1 = acc[mi][nj][rv * 2 + 1] - c1;
                    s = fmaf(d0, d0, s);
                    s = fmaf(d1, d1, s);
                }
                s += __shfl_xor_sync(0xffffffffu, s, 1);
                s += __shfl_xor_sync(0xffffffffu, s, 2);
                if (quad == cb) {
                    int row = wr * 32 + mi * 16 + rv * 8 + qrow;
                    int cg  = bx * 8 + wc * 4 + cb;
                    out[(((size_t)(b * 64 + cg)) << 14) + ptile + row] = expf(-3.125f * s);
                }
            }
}

extern "C" void kernel_launch(void* const* d_in, const int* in_sizes, int n_in,
                              void* d_out, int out_size) {
    const float *feat = nullptr, *w = nullptr, *m = nullptr, *Nb = nullptr;
    for (int i = 0; i < n_in; i++) {
        if (in_sizes[i] == 67108864)    feat = (const float*)d_in[i];
        else if (in_sizes[i] == 524288) w    = (const float*)d_in[i];
        else if (in_sizes[i] == 1024)   m    = (const float*)d_in[i];
        else if (in_sizes[i] == 64)     Nb   = (const float*)d_in[i];
    }
    float* out = (float*)d_out;

    static bool attr_set = false;
    if (!attr_set) {
        cudaFuncSetAttribute((const void*)duq_main,
                             cudaFuncAttributeMaxDynamicSharedMemorySize, SMEM_BYTES);
        attr_set = true;
    }

    prep_w<<<256, 256>>>(w);
    prep_feat<<<16384, 256>>>(feat);
    duq_main<<<dim3(8, 1024, 1), 256, SMEM_BYTES>>>(m, Nb, out);
}

// round 6
// speedup vs baseline: 1.2962x; 1.0708x over previous
#include <cuda_runtime.h>
#include <cuda_bf16.h>
#include <cstdint>

// ---------------- problem constants ----------------
#define HW       16384           // 128*128 pixels per image
#define N_KCHUNK 16              // K = 512 in chunks of 32

// ---------------- smem layout ----------------
// stage = A_hi(8K) A_lo(8K) B_hi(8K) B_lo(8K) = 32KB, 3 stages + cent
#define STAGE     32768
#define B_REGION  16384
#define CENT_OFF  (3 * STAGE)
#define SMEM_BYTES (CENT_OFF + 512)

// scratch: features pre-split to bf16 hi/lo in ldmatrix-canonical tiles.
// chunk (mt, kc) = 16KB: hi[8K] lo[8K]; 1024 mt * 16 kc = 256MB
__device__ uint4 g_feat[16777216];
// weights likewise: chunk (bx, kc) = 16KB; 8 * 16 = 2MB
__device__ uint4 g_w[131072];

// ---------------- helpers ----------------
__device__ __forceinline__ uint32_t smem_u32(const void* p) {
    uint32_t a;
    asm("{ .reg .u64 t; cvta.to.shared.u64 t, %1; cvt.u32.u64 %0, t; }" : "=r"(a) : "l"(p));
    return a;
}
#define CP_ASYNC16(dst, src) \
    asm volatile("cp.async.cg.shared.global [%0], [%1], 16;" :: "r"(dst), "l"(src) : "memory")
#define CP_COMMIT()  asm volatile("cp.async.commit_group;" ::: "memory")
#define CP_WAIT1()   asm volatile("cp.async.wait_group 1;" ::: "memory")

__device__ __forceinline__ void ldsm4(uint32_t* r, uint32_t addr) {
    asm volatile("ldmatrix.sync.aligned.m8n8.x4.shared.b16 {%0,%1,%2,%3}, [%4];"
        : "=r"(r[0]), "=r"(r[1]), "=r"(r[2]), "=r"(r[3]) : "r"(addr));
}
__device__ __forceinline__ void mma16816(float* d, const uint32_t* a, const uint32_t* b) {
    asm volatile("mma.sync.aligned.m16n8k16.row.col.f32.bf16.bf16.f32 "
        "{%0,%1,%2,%3}, {%4,%5,%6,%7}, {%8,%9}, {%0,%1,%2,%3};"
        : "+f"(d[0]), "+f"(d[1]), "+f"(d[2]), "+f"(d[3])
        : "r"(a[0]), "r"(a[1]), "r"(a[2]), "r"(a[3]), "r"(b[0]), "r"(b[1]));
}
__device__ __forceinline__ void split2(float x0, float x1, uint32_t& hi, uint32_t& lo) {
    __nv_bfloat16 h0 = __float2bfloat16(x0);
    __nv_bfloat16 h1 = __float2bfloat16(x1);
    __nv_bfloat16 l0 = __float2bfloat16(x0 - __bfloat162float(h0));
    __nv_bfloat16 l1 = __float2bfloat16(x1 - __bfloat162float(h1));
    hi = (uint32_t)__bfloat16_as_ushort(h0) | ((uint32_t)__bfloat16_as_ushort(h1) << 16);
    lo = (uint32_t)__bfloat16_as_ushort(l0) | ((uint32_t)__bfloat16_as_ushort(l1) << 16);
}

// ---------------- prep: weights -> hi/lo bf16 canonical tiles (n = c*16+e) ----
__global__ void prep_w(const float* __restrict__ w) {
    int idx = blockIdx.x * 256 + threadIdx.x;   // 0..65535 : n(1024) x k8(64)
    int n = idx >> 6, k8 = idx & 63;
    int e = n & 15, c = n >> 4;
    const float* src = w + (((size_t)(e * 64 + c)) << 9) + k8 * 8;
    uint32_t hiw[4], low[4];
    #pragma unroll
    for (int i = 0; i < 4; i++) split2(src[2 * i], src[2 * i + 1], hiw[i], low[i]);
    int bx = n >> 7, nl = n & 127, kc = k8 >> 2, k8l = k8 & 3;
    char* dst = (char*)g_w + ((size_t)(bx * 16 + kc)) * 16384;
    uint32_t off = (uint32_t)(((nl >> 3) * 4 + k8l) * 128 + (nl & 7) * 16);
    *(uint4*)(dst + off)        = make_uint4(hiw[0], hiw[1], hiw[2], hiw[3]);
    *(uint4*)(dst + 8192 + off) = make_uint4(low[0], low[1], low[2], low[3]);
}

// ---------------- prep: features -> hi/lo bf16 canonical tiles ----------------
__global__ void prep_feat(const float* __restrict__ feat) {
    __shared__ float s[32][128];
    int blk = blockIdx.x;                 // mt*16 + kc
    int mt = blk >> 4, kc = blk & 15;
    int b = mt >> 7, ptile = (mt & 127) << 7;
    const float* src = feat + (((size_t)b << 9) + kc * 32) * HW + ptile;
    int tid = threadIdx.x;
    int px = tid & 127, kh = tid >> 7;    // kh 0..1
    #pragma unroll
    for (int r = 0; r < 16; r++) {
        int k = r * 2 + kh;
        s[k][px] = src[(size_t)k * HW + px];
    }
    __syncthreads();
    char* dst = (char*)g_feat + (size_t)blk * 16384;
    #pragma unroll
    for (int j = 0; j < 2; j++) {
        int k8 = kh * 2 + j;
        uint32_t hiw[4], low[4];
        #pragma unroll
        for (int i = 0; i < 4; i++)
            split2(s[k8 * 8 + 2 * i][px], s[k8 * 8 + 2 * i + 1][px], hiw[i], low[i]);
        uint32_t off = (uint32_t)(((px >> 3) * 4 + k8) * 128 + (px & 7) * 16);
        *(uint4*)(dst + off)        = make_uint4(hiw[0], hiw[1], hiw[2], hiw[3]);
        *(uint4*)(dst + 8192 + off) = make_uint4(low[0], low[1], low[2], low[3]);
    }
}

// ---------------- main fused kernel ----------------
__global__ void __launch_bounds__(256, 2)
duq_main(const float* __restrict__ d_m, const float* __restrict__ d_N,
         float* __restrict__ out) {
    extern __shared__ char smem[];
    const uint32_t sb = smem_u32(smem);

    const int tid  = threadIdx.x;
    const int lane = tid & 31;
    const int wid  = tid >> 5;
    const int wr   = wid >> 1;        // warp m-row 0..3  (m offset wr*32)
    const int wc   = wid & 1;         // warp n-col 0..1  (n offset wc*64)
    const int bx   = blockIdx.x;      // n-tile 0..7
    const int mt   = blockIdx.y;      // m-tile 0..1023
    const int b    = mt >> 7;
    const int ptile = (mt & 127) << 7;

    // centroids: n_glob = bx*128 + i = c*16 + e
    float* centS = (float*)(smem + CENT_OFF);
    if (tid < 128) {
        int ng = bx * 128 + tid;
        centS[tid] = d_m[(ng & 15) * 64 + (ng >> 4)] / d_N[ng >> 4];
    }

    // per-thread source pointers for the chunk loader (advance by 16KB/chunk)
    const char* srcA = (const char*)(g_feat + ((size_t)(mt * 16) << 10)) + tid * 16;
    const char* srcB = (const char*)(g_w    + ((size_t)(bx * 16) << 10)) + tid * 16;
    const uint32_t dstT = sb + tid * 16;
    auto load_chunk = [&](int kc, uint32_t stByte) {
        const char* sa = srcA + ((size_t)kc << 14);
        const char* sp = srcB + ((size_t)kc << 14);
        #pragma unroll
        for (int it = 0; it < 4; it++)
            CP_ASYNC16(dstT + stByte + it * 4096, sa + it * 4096);
        #pragma unroll
        for (int it = 0; it < 4; it++)
            CP_ASYNC16(dstT + stByte + B_REGION + it * 4096, sp + it * 4096);
        CP_COMMIT();
    };

    // ldmatrix lane bases (canonical tiled layout, conflict-free)
    const int g = lane >> 3, r8 = lane & 7;
    const uint32_t baseA = sb + (uint32_t)((((wr * 4 + (g & 1)) * 4 + (g >> 1)) * 128) + r8 * 16);
    const uint32_t baseB = sb + (uint32_t)(B_REGION + (((wc * 8 + (g >> 1)) * 4 + (g & 1)) * 128) + r8 * 16);

    float acc[2][8][4];
    #pragma unroll
    for (int i = 0; i < 2; i++)
        #pragma unroll
        for (int j = 0; j < 8; j++)
            #pragma unroll
            for (int k = 0; k < 4; k++) acc[i][j][k] = 0.f;

    // one 16-K step: 12 ldsm.x4, 48 mma, B-frag registers reused hi->lo
    auto compute = [&](int ks, uint32_t st) {
        uint32_t ah[2][4], al[2][4], bb[8][2];
        const uint32_t aoff = baseA + st + ks * 256;
        const uint32_t boff = baseB + st + ks * 256;
        ldsm4(ah[0], aoff);
        ldsm4(ah[1], aoff + 1024);
        ldsm4(al[0], aoff + 8192);
        ldsm4(al[1], aoff + 8192 + 1024);
        #pragma unroll
        for (int t = 0; t < 4; t++) ldsm4(&bb[2 * t][0], boff + t * 1024);
        #pragma unroll
        for (int mi = 0; mi < 2; mi++)
            #pragma unroll
            for (int nj = 0; nj < 8; nj++) mma16816(acc[mi][nj], ah[mi], bb[nj]);  // hi*hi
        #pragma unroll
        for (int mi = 0; mi < 2; mi++)
            #pragma unroll
            for (int nj = 0; nj < 8; nj++) mma16816(acc[mi][nj], al[mi], bb[nj]);  // lo*hi
        #pragma unroll
        for (int t = 0; t < 4; t++) ldsm4(&bb[2 * t][0], boff + 8192 + t * 1024);  // reuse regs
        #pragma unroll
        for (int mi = 0; mi < 2; mi++)
            #pragma unroll
            for (int nj = 0; nj < 8; nj++) mma16816(acc[mi][nj], ah[mi], bb[nj]);  // hi*lo
    };

    // ---- prologue: chunks 0,1 into stages 0,1 ----
    load_chunk(0, 0);
    load_chunk(1, STAGE);

    // ---- main loop: 3-stage, one barrier per chunk ----
    uint32_t s0 = 0, s1 = STAGE, s2 = 2 * STAGE;  // rotate: s0=compute, s2=load dest
    for (int kc = 0; kc < N_KCHUNK; kc++) {
        CP_WAIT1();
        __syncthreads();
        if (kc + 2 < N_KCHUNK) load_chunk(kc + 2, s2);
        else CP_COMMIT();     // keep wait_group accounting uniform
        compute(0, s0);
        compute(1, s0);
        uint32_t t = s0; s0 = s1; s1 = s2; s2 = t;
    }

    // ---- epilogue: S = sum_e (emb - cent)^2 over 16 contiguous n, exp ----
    const int quad = lane & 3, qrow = lane >> 2;
    #pragma unroll
    for (int mi = 0; mi < 2; mi++)
        #pragma unroll
        for (int rv = 0; rv < 2; rv++)
            #pragma unroll
            for (int cb = 0; cb < 4; cb++) {
                float s = 0.f;
                #pragma unroll
                for (int tt = 0; tt < 2; tt++) {
                    int nj = cb * 2 + tt;
                    int n0 = wc * 64 + nj * 8 + quad * 2;
                    float c0 = centS[n0], c1 = centS[n0 + 1];
                    float d0 = acc[mi][nj][rv * 2 + 0] - c0;
                    float d1 = acc[mi][nj][rv * 2 + 1] - c1;
                    s = fmaf(d0, d0, s);
                    s = fmaf(d1, d1, s);
                }
                s += __shfl_xor_sync(0xffffffffu, s, 1);
                s += __shfl_xor_sync(0xffffffffu, s, 2);
                if (quad == cb) {
                    int row = wr * 32 + mi * 16 + rv * 8 + qrow;
                    int cg  = bx * 8 + wc * 4 + cb;
                    out[(((size_t)(b * 64 + cg)) << 14) + ptile + row] = expf(-3.125f * s);
                }
            }
}

extern "C" void kernel_launch(void* const* d_in, const int* in_sizes, int n_in,
                              void* d_out, int out_size) {
    const float *feat = nullptr, *w = nullptr, *m = nullptr, *Nb = nullptr;
    for (int i = 0; i < n_in; i++) {
        if (in_sizes[i] == 67108864)    feat = (const float*)d_in[i];
        else if (in_sizes[i] == 524288) w    = (const float*)d_in[i];
        else if (in_sizes[i] == 1024)   m    = (const float*)d_in[i];
        else if (in_sizes[i] == 64)     Nb   = (const float*)d_in[i];
    }
    float* out = (float*)d_out;

    static bool attr_set = false;
    if (!attr_set) {
        cudaFuncSetAttribute((const void*)duq_main,
                             cudaFuncAttributeMaxDynamicSharedMemorySize, SMEM_BYTES);
        attr_set = true;
    }

    prep_w<<<256, 256>>>(w);
    prep_feat<<<16384, 256>>>(feat);
    duq_main<<<dim3(8, 1024, 1), 256, SMEM_BYTES>>>(m, Nb, out);
}